// round 11
// baseline (speedup 1.0000x reference)
#include <cuda_runtime.h>

#define NB   128
#define ND   32
#define NP   16384
#define NCTA 148       // 1 CTA per SM, one wave -> grid barrier safe
#define THREADS 256
#define PSLOTS 128     // zero-padded pairs per CTA (110-111 real)
#define PSTRIDE 33

typedef unsigned long long u64;

// ---- dynamic smem layout (bytes) ----
// Region A : coefdup [64 rows x 1040 B]  (phase B)  ALIASED BY  W [128 x 528 B] (phase B epi / C)
// Region XX: xx      [64 rows x 528 B]              ALIASED BY  den_half[256]f, s_red[33*..]f
// Region KC: Kcdup   [128 rows x 528 B]             ALIASED BY  AC [64 rows x 512 B]
#define OFF_A    0
#define SZ_A     67584            // max(64*1040, 128*528)
#define OFF_XX   (OFF_A + SZ_A)
#define SZ_XX    33792            // 64*528
#define OFF_KC   (OFF_XX + SZ_XX)
#define SZ_KC    67584            // 128*528
#define OFF_P0   (OFF_KC + SZ_KC)
#define OFF_LAM  (OFF_P0 + 512)
#define SMEM_TOTAL (OFF_LAM + 512)   // 169,984 B

__device__ float g_partial[NCTA * NB * PSTRIDE];
__device__ unsigned int g_arrive;   // monotonic across graph replays

__device__ __forceinline__ u64 fma2(u64 a, u64 b, u64 c) {
    u64 d;
    asm("fma.rn.f32x2 %0, %1, %2, %3;" : "=l"(d) : "l"(a), "l"(b), "l"(c));
    return d;
}
__device__ __forceinline__ u64 pack2(float lo, float hi) {
    u64 d;
    asm("mov.b64 %0, {%1, %2};" : "=l"(d) : "f"(lo), "f"(hi));
    return d;
}
__device__ __forceinline__ void unpack2(u64 v, float& lo, float& hi) {
    asm("mov.b64 {%0, %1}, %2;" : "=f"(lo), "=f"(hi) : "l"(v));
}

// ---------------------------------------------------------------------------
// GEMM-structured fused kernel.
//  A) per-pair coefficients -> coefdup[k][p] (dup u64), Kcdup[p][n] (dup u64),
//     p0[p], lam[p]; xx[k][b-pair] = packed [x^2 | x].
//  B) GEMM1: logw[p][b] = coef . xx  (warp = 16 p's x all 128 b; acc 32 u64)
//     epi: w = expf(clip(logw)) * lam -> W[p][b] (aliases coefdup, after sync)
//  C) GEMM2: AC[n][b] = Kc . W  (warp = 8 n's x all 128 b)
//     den[b] = column sum of W (two fixed halves)
//     num[b,n] = x[b,n]*AC[n][b] + AC[32+n][b]
//  D) grid barrier -> cross-CTA reduce (CTA c reduces batch c), out = num/den
// All reduction orders fixed -> deterministic.
// ---------------------------------------------------------------------------
__global__ __launch_bounds__(THREADS, 1)
void gmm_all(const float* __restrict__ X,   const float* __restrict__ t_ptr,
             const float* __restrict__ Mu0, const float* __restrict__ Mu1,
             const float* __restrict__ S0,  const float* __restrict__ S1,
             const float* __restrict__ Lam, float* __restrict__ out)
{
    extern __shared__ char sm[];

    const int tid  = threadIdx.x;
    const int wid  = tid >> 5;      // 0..7
    const int lane = tid & 31;
    const int cta  = blockIdx.x;

    const int basecnt = NP / NCTA;            // 110
    const int rem     = NP - basecnt * NCTA;  // 104
    const int start   = cta * basecnt + (cta < rem ? cta : rem);
    const int np      = basecnt + (cta < rem ? 1 : 0);

    const float t     = t_ptr[0];
    const float omt   = 1.0f - t;
    const float e2    = 0.25f;
    const float e4    = 0.0625f;
    const float tt    = t * t;
    const float omt2  = omt * omt;
    const float t2omt = 2.0f * t * omt;
    const float e2tot = e2 * t * omt;

    // ---- fill xx: row d = x^2 (d<32), row 32+d = x; col = batch pair ----
    {
        const int bp = tid & 63;          // u64 column (batches 2bp, 2bp+1)
        const int d0 = tid >> 6;          // 0..3
        const float* x0p = X + (2 * bp) * ND;
        const float* x1p = X + (2 * bp + 1) * ND;
        #pragma unroll
        for (int m = 0; m < 8; m++) {
            const int d = d0 + 4 * m;
            const float x0 = x0p[d], x1 = x1p[d];
            *(u64*)(sm + OFF_XX + d * 528 + bp * 8)        = pack2(x0 * x0, x1 * x1);
            *(u64*)(sm + OFF_XX + (32 + d) * 528 + bp * 8) = pack2(x0, x1);
        }
    }

    // ---- phase A: coefficients (warp per pair-slot, lane per dim) ----
    for (int sl = wid; sl < PSLOTS; sl += 8) {
        float a = 0.f, p1v = 0.f, K = 0.f, c = 0.f, p0s = 0.f, lam = 0.f;
        if (sl < np) {
            const int ij = start + sl;
            const int i  = ij >> 7;
            const int j  = ij & 127;
            lam = Lam[ij];

            const float s0 = S0[i * ND + lane];
            const float s1 = S1[j * ND + lane];
            const float Ds = sqrtf(fmaf(4.0f * s0, s1, e4));
            const float Cs = 0.5f * (Ds - e2);
            const float Sigma = omt2 * s0 + tt * s1 + t2omt * Cs + e2tot;
            const float St = (t * s1 + omt * Cs) - (omt * s0 + t * Cs) - e2 * t;

            const float mu0 = Mu0[i * ND + lane];
            const float mu1 = Mu1[j * ND + lane];
            const float mut = fmaf(t, mu1, omt * mu0);

            const float inv = __fdividef(1.0f, Sigma);
            K   = St * inv;
            a   = -0.5f * inv;
            p1v = inv * mut;
            c   = (mu1 - mu0) - K * mut;

            float p0 = fmaf(a * mut, mut, -0.5f * __logf(Sigma));
            #pragma unroll
            for (int off = 16; off; off >>= 1)
                p0 += __shfl_xor_sync(0xFFFFFFFFu, p0, off);
            p0s = p0;
        }
        *(u64*)(sm + OFF_A  + lane * 1040 + sl * 8)        = pack2(a, a);
        *(u64*)(sm + OFF_A  + (32 + lane) * 1040 + sl * 8) = pack2(p1v, p1v);
        *(u64*)(sm + OFF_KC + sl * 528 + lane * 8)         = pack2(K, K);
        *(u64*)(sm + OFF_KC + sl * 528 + (32 + lane) * 8)  = pack2(c, c);
        if (lane == 0) {
            ((float*)(sm + OFF_P0))[sl]  = p0s;
            ((float*)(sm + OFF_LAM))[sl] = lam;
        }
    }
    __syncthreads();

    // ---- phase B: GEMM1. warp covers p = wid*16..+15, all 128 batches ----
    u64 acc[16][2];
    {
        const float* p0v = (const float*)(sm + OFF_P0);
        #pragma unroll
        for (int pi = 0; pi < 16; pi++) {
            const float v = p0v[wid * 16 + pi];
            acc[pi][0] = acc[pi][1] = pack2(v, v);
        }
        #pragma unroll 4
        for (int k = 0; k < 64; k++) {
            const ulonglong2 bv =
                *(const ulonglong2*)(sm + OFF_XX + k * 528 + lane * 16);
            const char* crow = sm + OFF_A + k * 1040 + wid * 128;
            #pragma unroll
            for (int h = 0; h < 8; h++) {
                const ulonglong2 av = *(const ulonglong2*)(crow + h * 16);
                acc[2*h][0]   = fma2(av.x, bv.x, acc[2*h][0]);
                acc[2*h][1]   = fma2(av.x, bv.y, acc[2*h][1]);
                acc[2*h+1][0] = fma2(av.y, bv.x, acc[2*h+1][0]);
                acc[2*h+1][1] = fma2(av.y, bv.y, acc[2*h+1][1]);
            }
        }
    }
    __syncthreads();   // all coefdup reads done; region A becomes W

    // ---- phase B epilogue: w = exp(clip(logw)) * lam -> W[p][b] ----
    {
        const float* lamv = (const float*)(sm + OFF_LAM);
        #pragma unroll
        for (int pi = 0; pi < 16; pi++) {
            const int p = wid * 16 + pi;
            const float lam = lamv[p];
            float f0, f1, f2, f3;
            unpack2(acc[pi][0], f0, f1);
            unpack2(acc[pi][1], f2, f3);
            f0 = __expf(fminf(fmaxf(f0, -50.f), 50.f)) * lam;
            f1 = __expf(fminf(fmaxf(f1, -50.f), 50.f)) * lam;
            f2 = __expf(fminf(fmaxf(f2, -50.f), 50.f)) * lam;
            f3 = __expf(fminf(fmaxf(f3, -50.f), 50.f)) * lam;
            ulonglong2 wv;
            wv.x = pack2(f0, f1);
            wv.y = pack2(f2, f3);
            *(ulonglong2*)(sm + OFF_A + p * 528 + lane * 16) = wv;
        }
    }
    __syncthreads();

    // ---- phase C: GEMM2. warp covers n = wid*8..+7, all 128 batches ----
    u64 ac[8][2];
    #pragma unroll
    for (int h = 0; h < 8; h++) ac[h][0] = ac[h][1] = 0ull;
    {
        #pragma unroll 4
        for (int p = 0; p < 128; p++) {
            const ulonglong2 bv =
                *(const ulonglong2*)(sm + OFF_A + p * 528 + lane * 16);
            const char* kcrow = sm + OFF_KC + p * 528 + wid * 64;
            #pragma unroll
            for (int h = 0; h < 4; h++) {
                const ulonglong2 av = *(const ulonglong2*)(kcrow + h * 16);
                ac[2*h][0]   = fma2(av.x, bv.x, ac[2*h][0]);
                ac[2*h][1]   = fma2(av.x, bv.y, ac[2*h][1]);
                ac[2*h+1][0] = fma2(av.y, bv.x, ac[2*h+1][0]);
                ac[2*h+1][1] = fma2(av.y, bv.y, ac[2*h+1][1]);
            }
        }
    }
    __syncthreads();   // Kcdup reads done; region KC becomes AC

    // store AC rows (n stride 512 B)
    #pragma unroll
    for (int h = 0; h < 8; h++) {
        const int n = wid * 8 + h;
        ulonglong2 v;
        v.x = ac[h][0];
        v.y = ac[h][1];
        *(ulonglong2*)(sm + OFF_KC + n * 512 + lane * 16) = v;
    }
    // den halves: thread (b = tid>>1, half = tid&1) sums 64 p's (fixed order)
    {
        const int b  = tid >> 1;
        const int hf = tid & 1;
        float s = 0.f;
        #pragma unroll 8
        for (int p = hf * 64; p < hf * 64 + 64; p++)
            s += *(const float*)(sm + OFF_A + p * 528 + b * 4);
        ((float*)(sm + OFF_XX))[tid] = s;     // index = b*2 + hf == tid
    }
    __syncthreads();

    // ---- per-CTA partial: num[b,n] = x*A + C ; den = half0 + half1 ----
    {
        const int b  = tid >> 1;
        const int nh = (tid & 1) * 16;
        float* gp = g_partial + (size_t)cta * NB * PSTRIDE + b * PSTRIDE;
        #pragma unroll
        for (int n = nh; n < nh + 16; n++) {
            const float A = *(const float*)(sm + OFF_KC + n * 512 + b * 4);
            const float C = *(const float*)(sm + OFF_KC + (32 + n) * 512 + b * 4);
            gp[n] = fmaf(X[b * ND + n], A, C);
        }
        if ((tid & 1) == 0) {
            const float den = ((float*)(sm + OFF_XX))[2 * b]
                            + ((float*)(sm + OFF_XX))[2 * b + 1];
            gp[32] = den;
        }
    }

    // ---- grid-wide arrival barrier ----
    __threadfence();
    __syncthreads();
    if (tid == 0) {
        const unsigned ticket = atomicAdd(&g_arrive, 1u);
        if (cta < NB) {
            const unsigned target = (ticket / NCTA + 1u) * NCTA;
            unsigned v;
            do {
                asm volatile("ld.acquire.gpu.global.u32 %0, [%1];"
                             : "=r"(v) : "l"(&g_arrive));
            } while (v < target);
        }
    }
    if (cta >= NB) return;
    __syncthreads();

    // ---- final reduce: CTA owns batch = cta ----
    {
        float* s_red = (float*)(sm + OFF_XX);
        const int w2i = tid >> 5;     // 0..7
        const int ln  = tid & 31;
        const float* bp = g_partial + cta * PSTRIDE;

        float a5[5];
        const int nn[5] = {w2i, w2i + 8, w2i + 16, w2i + 24, 32};
        #pragma unroll
        for (int r = 0; r < 5; r++) {
            float acc5 = 0.f;
            #pragma unroll
            for (int i = 0; i < 5; i++) {
                const int c = ln + 32 * i;
                if (c < NCTA)
                    acc5 += __ldcg(bp + (size_t)c * NB * PSTRIDE + nn[r]);
            }
            #pragma unroll
            for (int off = 16; off; off >>= 1)
                acc5 += __shfl_xor_sync(0xFFFFFFFFu, acc5, off);
            a5[r] = acc5;
        }
        __syncthreads();
        if (ln == 0) {
            s_red[nn[0]] = a5[0];
            s_red[nn[1]] = a5[1];
            s_red[nn[2]] = a5[2];
            s_red[nn[3]] = a5[3];
            if (w2i == 0) s_red[32] = a5[4];
        }
    }
    __syncthreads();

    if (tid < ND) {
        const float* s_red = (const float*)(sm + OFF_XX);
        out[cta * ND + tid] = s_red[tid] / s_red[32];
    }
}

// ---------------------------------------------------------------------------
extern "C" void kernel_launch(void* const* d_in, const int* in_sizes, int n_in,
                              void* d_out, int out_size)
{
    const float* X   = (const float*)d_in[0];
    const float* t   = (const float*)d_in[1];
    const float* Mu0 = (const float*)d_in[2];
    const float* Mu1 = (const float*)d_in[3];
    const float* S0  = (const float*)d_in[4];
    const float* S1  = (const float*)d_in[5];
    const float* Lam = (const float*)d_in[6];
    float* out = (float*)d_out;

    cudaFuncSetAttribute(gmm_all,
                         cudaFuncAttributeMaxDynamicSharedMemorySize, SMEM_TOTAL);
    gmm_all<<<NCTA, THREADS, SMEM_TOTAL>>>(X, t, Mu0, Mu1, S0, S1, Lam, out);
}

// round 12
// speedup vs baseline: 1.0617x; 1.0617x over previous
#include <cuda_runtime.h>

#define NB   128
#define ND   32
#define NP   16384
#define NCTA 148       // 1 CTA per SM, one wave -> grid barrier safe
#define THREADS 512
#define PSLOTS 128     // zero-padded pairs per CTA (110-111 real)
#define PSTRIDE 33

typedef unsigned long long u64;

// ---- dynamic smem layout (bytes) ----
// Region A : coefdup [64 rows x 1040 B] (phase B)  ALIASED BY  W [128 x 528 B]
// Region XX: xx      [64 rows x 528 B]             ALIASED BY  den quads / s_red
// Region KC: Kcdup   [128 rows x 528 B]            ALIASED BY  AC [64 rows x 512 B]
#define OFF_A    0
#define SZ_A     67584
#define OFF_XX   (OFF_A + SZ_A)
#define SZ_XX    33792
#define OFF_KC   (OFF_XX + SZ_XX)
#define SZ_KC    67584
#define OFF_P0   (OFF_KC + SZ_KC)
#define OFF_LAM  (OFF_P0 + 512)
#define SMEM_TOTAL (OFF_LAM + 512)   // 169,984 B

__device__ float g_partial[NCTA * NB * PSTRIDE];
__device__ unsigned int g_arrive;   // monotonic across graph replays

__device__ __forceinline__ u64 fma2(u64 a, u64 b, u64 c) {
    u64 d;
    asm("fma.rn.f32x2 %0, %1, %2, %3;" : "=l"(d) : "l"(a), "l"(b), "l"(c));
    return d;
}
__device__ __forceinline__ u64 pack2(float lo, float hi) {
    u64 d;
    asm("mov.b64 %0, {%1, %2};" : "=l"(d) : "f"(lo), "f"(hi));
    return d;
}
__device__ __forceinline__ void unpack2(u64 v, float& lo, float& hi) {
    asm("mov.b64 {%0, %1}, %2;" : "=f"(lo), "=f"(hi) : "l"(v));
}

// ---------------------------------------------------------------------------
// GEMM-structured fused kernel, 16 warps (R11 structure, 2x warps, regs/2):
//  A) coefficients -> coefdup[k][p], Kcdup[p][n], p0[p], lam[p]; xx[k][b].
//  B) GEMM1 logw[p][b]: warp = 8 p's x 128 b (acc 16 u64).
//     epi: w = expf(clip(logw))*lam -> W (aliases coefdup after sync).
//  C) GEMM2 AC[n][b]: warp = 4 rows x 128 b. den = 4 fixed quarters.
//     num[b,n] = x*A + C.
//  D) grid barrier -> cross-CTA reduce (CTA c owns batch c), out = num/den.
// All reduction orders fixed -> deterministic.
// ---------------------------------------------------------------------------
__global__ __launch_bounds__(THREADS, 1)
void gmm_all(const float* __restrict__ X,   const float* __restrict__ t_ptr,
             const float* __restrict__ Mu0, const float* __restrict__ Mu1,
             const float* __restrict__ S0,  const float* __restrict__ S1,
             const float* __restrict__ Lam, float* __restrict__ out)
{
    extern __shared__ char sm[];

    const int tid  = threadIdx.x;
    const int wid  = tid >> 5;      // 0..15
    const int lane = tid & 31;
    const int cta  = blockIdx.x;

    const int basecnt = NP / NCTA;            // 110
    const int rem     = NP - basecnt * NCTA;  // 104
    const int start   = cta * basecnt + (cta < rem ? cta : rem);
    const int np      = basecnt + (cta < rem ? 1 : 0);

    const float t     = t_ptr[0];
    const float omt   = 1.0f - t;
    const float e2    = 0.25f;
    const float e4    = 0.0625f;
    const float tt    = t * t;
    const float omt2  = omt * omt;
    const float t2omt = 2.0f * t * omt;
    const float e2tot = e2 * t * omt;

    // ---- fill xx: row d = x^2 (d<32), row 32+d = x; col = batch pair ----
    {
        const int bp = tid & 63;          // u64 column (batches 2bp, 2bp+1)
        const int d0 = tid >> 6;          // 0..7
        const float* x0p = X + (2 * bp) * ND;
        const float* x1p = X + (2 * bp + 1) * ND;
        #pragma unroll
        for (int m = 0; m < 4; m++) {
            const int d = d0 + 8 * m;
            const float x0 = x0p[d], x1 = x1p[d];
            *(u64*)(sm + OFF_XX + d * 528 + bp * 8)        = pack2(x0 * x0, x1 * x1);
            *(u64*)(sm + OFF_XX + (32 + d) * 528 + bp * 8) = pack2(x0, x1);
        }
    }

    // ---- phase A: coefficients (warp per pair-slot, lane per dim) ----
    for (int sl = wid; sl < PSLOTS; sl += 16) {
        float a = 0.f, p1v = 0.f, K = 0.f, c = 0.f, p0s = 0.f, lam = 0.f;
        if (sl < np) {
            const int ij = start + sl;
            const int i  = ij >> 7;
            const int j  = ij & 127;
            lam = Lam[ij];

            const float s0 = S0[i * ND + lane];
            const float s1 = S1[j * ND + lane];
            const float Ds = sqrtf(fmaf(4.0f * s0, s1, e4));
            const float Cs = 0.5f * (Ds - e2);
            const float Sigma = omt2 * s0 + tt * s1 + t2omt * Cs + e2tot;
            const float St = (t * s1 + omt * Cs) - (omt * s0 + t * Cs) - e2 * t;

            const float mu0 = Mu0[i * ND + lane];
            const float mu1 = Mu1[j * ND + lane];
            const float mut = fmaf(t, mu1, omt * mu0);

            const float inv = __fdividef(1.0f, Sigma);
            K   = St * inv;
            a   = -0.5f * inv;
            p1v = inv * mut;
            c   = (mu1 - mu0) - K * mut;

            float p0 = fmaf(a * mut, mut, -0.5f * __logf(Sigma));
            #pragma unroll
            for (int off = 16; off; off >>= 1)
                p0 += __shfl_xor_sync(0xFFFFFFFFu, p0, off);
            p0s = p0;
        }
        *(u64*)(sm + OFF_A  + lane * 1040 + sl * 8)        = pack2(a, a);
        *(u64*)(sm + OFF_A  + (32 + lane) * 1040 + sl * 8) = pack2(p1v, p1v);
        *(u64*)(sm + OFF_KC + sl * 528 + lane * 8)         = pack2(K, K);
        *(u64*)(sm + OFF_KC + sl * 528 + (32 + lane) * 8)  = pack2(c, c);
        if (lane == 0) {
            ((float*)(sm + OFF_P0))[sl]  = p0s;
            ((float*)(sm + OFF_LAM))[sl] = lam;
        }
    }
    __syncthreads();

    // ---- phase B: GEMM1. warp covers p = wid*8..+7, all 128 batches ----
    u64 acc[8][2];
    {
        const float* p0v = (const float*)(sm + OFF_P0);
        #pragma unroll
        for (int pi = 0; pi < 8; pi++) {
            const float v = p0v[wid * 8 + pi];
            acc[pi][0] = acc[pi][1] = pack2(v, v);
        }
        #pragma unroll 4
        for (int k = 0; k < 64; k++) {
            const ulonglong2 bv =
                *(const ulonglong2*)(sm + OFF_XX + k * 528 + lane * 16);
            const char* crow = sm + OFF_A + k * 1040 + wid * 64;
            #pragma unroll
            for (int h = 0; h < 4; h++) {
                const ulonglong2 av = *(const ulonglong2*)(crow + h * 16);
                acc[2*h][0]   = fma2(av.x, bv.x, acc[2*h][0]);
                acc[2*h][1]   = fma2(av.x, bv.y, acc[2*h][1]);
                acc[2*h+1][0] = fma2(av.y, bv.x, acc[2*h+1][0]);
                acc[2*h+1][1] = fma2(av.y, bv.y, acc[2*h+1][1]);
            }
        }
    }
    __syncthreads();   // all coefdup reads done; region A becomes W

    // ---- phase B epilogue: w = exp(clip(logw)) * lam -> W[p][b] ----
    {
        const float* lamv = (const float*)(sm + OFF_LAM);
        #pragma unroll
        for (int pi = 0; pi < 8; pi++) {
            const int p = wid * 8 + pi;
            const float lam = lamv[p];
            float f0, f1, f2, f3;
            unpack2(acc[pi][0], f0, f1);
            unpack2(acc[pi][1], f2, f3);
            f0 = __expf(fminf(fmaxf(f0, -50.f), 50.f)) * lam;
            f1 = __expf(fminf(fmaxf(f1, -50.f), 50.f)) * lam;
            f2 = __expf(fminf(fmaxf(f2, -50.f), 50.f)) * lam;
            f3 = __expf(fminf(fmaxf(f3, -50.f), 50.f)) * lam;
            ulonglong2 wv;
            wv.x = pack2(f0, f1);
            wv.y = pack2(f2, f3);
            *(ulonglong2*)(sm + OFF_A + p * 528 + lane * 16) = wv;
        }
    }
    __syncthreads();

    // ---- phase C: GEMM2. warp covers rows wid*4..+3 of [K|c], 128 b ----
    u64 ac[4][2];
    #pragma unroll
    for (int h = 0; h < 4; h++) ac[h][0] = ac[h][1] = 0ull;
    {
        #pragma unroll 4
        for (int p = 0; p < 128; p++) {
            const ulonglong2 bv =
                *(const ulonglong2*)(sm + OFF_A + p * 528 + lane * 16);
            const char* kcrow = sm + OFF_KC + p * 528 + wid * 32;
            #pragma unroll
            for (int h = 0; h < 2; h++) {
                const ulonglong2 av = *(const ulonglong2*)(kcrow + h * 16);
                ac[2*h][0]   = fma2(av.x, bv.x, ac[2*h][0]);
                ac[2*h][1]   = fma2(av.x, bv.y, ac[2*h][1]);
                ac[2*h+1][0] = fma2(av.y, bv.x, ac[2*h+1][0]);
                ac[2*h+1][1] = fma2(av.y, bv.y, ac[2*h+1][1]);
            }
        }
    }
    // den quarters: thread (b = tid>>2, qa = tid&3) sums 32 p's (fixed order)
    // (reads W region; write target OFF_XX is dead after GEMM1)
    {
        const int b  = tid >> 2;
        const int qa = tid & 3;
        float s = 0.f;
        #pragma unroll 8
        for (int p = qa * 32; p < qa * 32 + 32; p++)
            s += *(const float*)(sm + OFF_A + p * 528 + b * 4);
        ((float*)(sm + OFF_XX))[tid] = s;      // index = b*4 + qa
    }
    __syncthreads();   // Kcdup + W reads done; region KC becomes AC

    // store AC rows (row stride 512 B)
    #pragma unroll
    for (int h = 0; h < 4; h++) {
        const int n = wid * 4 + h;
        ulonglong2 v;
        v.x = ac[h][0];
        v.y = ac[h][1];
        *(ulonglong2*)(sm + OFF_KC + n * 512 + lane * 16) = v;
    }
    __syncthreads();

    // ---- per-CTA partial: num[b,n] = x*A + C ; den = 4 quarters ----
    {
        const int b  = tid >> 2;
        const int nq = (tid & 3) * 8;
        float* gp = g_partial + (size_t)cta * NB * PSTRIDE + b * PSTRIDE;
        #pragma unroll
        for (int n = nq; n < nq + 8; n++) {
            const float A = *(const float*)(sm + OFF_KC + n * 512 + b * 4);
            const float C = *(const float*)(sm + OFF_KC + (32 + n) * 512 + b * 4);
            gp[n] = fmaf(X[b * ND + n], A, C);
        }
        if ((tid & 3) == 0) {
            const float* dq = (const float*)(sm + OFF_XX) + b * 4;
            gp[32] = ((dq[0] + dq[1]) + (dq[2] + dq[3]));
        }
    }

    // ---- grid-wide arrival barrier ----
    __threadfence();
    __syncthreads();
    if (tid == 0) {
        const unsigned ticket = atomicAdd(&g_arrive, 1u);
        if (cta < NB) {
            const unsigned target = (ticket / NCTA + 1u) * NCTA;
            unsigned v;
            do {
                asm volatile("ld.acquire.gpu.global.u32 %0, [%1];"
                             : "=r"(v) : "l"(&g_arrive));
            } while (v < target);
        }
    }
    if (cta >= NB) return;
    __syncthreads();

    // ---- final reduce: CTA owns batch = cta (16 warps, 2 n's each + den) ----
    {
        float* s_red = (float*)(sm + OFF_XX);
        const int w2i = tid >> 5;     // 0..15
        const int ln  = tid & 31;
        const float* bp = g_partial + cta * PSTRIDE;

        float a3[3];
        const int nn[3] = {w2i, w2i + 16, 32};
        #pragma unroll
        for (int r = 0; r < 3; r++) {
            float accv = 0.f;
            #pragma unroll
            for (int i = 0; i < 5; i++) {
                const int c = ln + 32 * i;
                if (c < NCTA)
                    accv += __ldcg(bp + (size_t)c * NB * PSTRIDE + nn[r]);
            }
            #pragma unroll
            for (int off = 16; off; off >>= 1)
                accv += __shfl_xor_sync(0xFFFFFFFFu, accv, off);
            a3[r] = accv;
        }
        __syncthreads();
        if (ln == 0) {
            s_red[nn[0]] = a3[0];
            s_red[nn[1]] = a3[1];
            if (w2i == 0) s_red[32] = a3[2];
        }
    }
    __syncthreads();

    if (tid < ND) {
        const float* s_red = (const float*)(sm + OFF_XX);
        out[cta * ND + tid] = s_red[tid] / s_red[32];
    }
}

// ---------------------------------------------------------------------------
extern "C" void kernel_launch(void* const* d_in, const int* in_sizes, int n_in,
                              void* d_out, int out_size)
{
    const float* X   = (const float*)d_in[0];
    const float* t   = (const float*)d_in[1];
    const float* Mu0 = (const float*)d_in[2];
    const float* Mu1 = (const float*)d_in[3];
    const float* S0  = (const float*)d_in[4];
    const float* S1  = (const float*)d_in[5];
    const float* Lam = (const float*)d_in[6];
    float* out = (float*)d_out;

    cudaFuncSetAttribute(gmm_all,
                         cudaFuncAttributeMaxDynamicSharedMemorySize, SMEM_TOTAL);
    gmm_all<<<NCTA, THREADS, SMEM_TOTAL>>>(X, t, Mu0, Mu1, S0, S1, Lam, out);
}